// round 12
// baseline (speedup 1.0000x reference)
#include <cuda_runtime.h>

// HH_Synaptic, Round 12: R11 body + 2 warps per SMSP via half-filled warps.
// 16384 chains = 1024 warps x 16 active lanes. Two co-resident warps per
// SMSP interleave on the issue port, covering each other's RAW/MUFU stalls
// (a single warp cannot fill its own in-order stall shadows).
// 128 blocks x 256 threads; lanes >= 16 exit immediately.

#define N_DIM 2000
#define L_DIM 1024
#define PF    4

__device__ __forceinline__ float ex2f_(float x){ float r; asm("ex2.approx.f32 %0, %1;" : "=f"(r) : "f"(x)); return r; }
__device__ __forceinline__ float rcpf_(float x){ float r; asm("rcp.approx.f32 %0, %1;" : "=f"(r) : "f"(x)); return r; }

__global__ __launch_bounds__(256, 1)
void hh_synaptic_kernel(const float* __restrict__ z, float* __restrict__ out) {
    const int lane = threadIdx.x & 31;
    if (lane >= 16) return;                       // half-filled warps
    const int warp = (blockIdx.x * blockDim.x + threadIdx.x) >> 5;  // 0..1023
    const int chain = warp * 16 + lane;           // 0 .. 16383
    const int b = chain >> 10;
    const int l = chain & (L_DIM - 1);

    const float* zp = z   + (size_t)b * (N_DIM * L_DIM) + l;
    float*       op = out + (size_t)b * (N_DIM * L_DIM) + l;

    const float LOG2E = 1.4426950408889634f;
    const float c9    = LOG2E / 9.0f;
    const float c12   = LOG2E / 12.0f;
    const float cSIG  = LOG2E / 3.0f;
    const float cAH01 = 0.01f * 0.25f * expf(-56.0f / 12.0f);

    // Singularity-patch constants (reference's exact-equality cases): x' = k*x + c
    const float pN_ = 0.01f*(0.18f+0.08f),  pM_ = 0.01f*(1.638f+1.16f);
    const float kNp = (1.0f-pN_)/(1.0f+pN_), cNp = (0.02f*0.18f)/(1.0f+pN_);
    const float kMp = (1.0f-pM_)/(1.0f+pM_), cMp = (0.02f*1.638f)/(1.0f+pM_);

    // State
    float V = -70.0f;
    float m = 0.0f, n = 0.0f, h = 1.0f, y = 0.0f;
    float yG  = 1.003f;          // 1.003 + 0.01*y   (staged off-spine)
    float h40 = 40.0f;           // 40*h             (staged off-spine)

    // Pipelined output: argS for row 0 (V=-70) stores at top of first iteration
    float argS_prev = -(V + 20.0f) * cSIG;
    float* olPrev = op;

    // z prefetch ring: step k consumes z index (k-1)
    float zbuf[PF];
    #pragma unroll
    for (int j = 0; j < PF; ++j)
        zbuf[j] = __ldg(zp + (size_t)j * L_DIM);

    #pragma unroll 4
    for (int k = 1; k < N_DIM; ++k) {
        float zc = zbuf[0];
        #pragma unroll
        for (int j = 0; j < PF - 1; ++j) zbuf[j] = zbuf[j + 1];
        int pidx = min(k - 1 + PF, N_DIM - 1);
        zbuf[PF - 1] = __ldg(zp + (size_t)pidx * L_DIM);

        // ---- head: pow chain, then the V rcp ----
        float mm   = m * m;
        float mh   = m * h40;
        float pow1 = mm * mh;                            // GNA*m^3*h
        float n2   = n * n;
        float n35  = 35.0f * n2;
        float pow2 = n2 * n35;                           // GK*n^4
        float psum = pow1 + pow2;
        float Gp   = fmaf(0.01f, psum, yG);              // 1 + G
        float r    = rcpf_(Gp);

        // ---- rcp shadow: previous step's output sigmoid + store ----
        float eS   = ex2f_(argS_prev);
        float outP = rcpf_(1.0f + eS);
        *olPrev = outP;
        olPrev += L_DIM;

        // ---- rcp shadow: y-rail (V-independent), series rcp, pY <= 0.011 ----
        float pY = fmaf(0.01f, zc, 0.001f);
        float rY = fmaf(pY, fmaf(pY, 1.0f - pY, -1.0f), 1.0f);
        float yn = fmaf(zc, 0.02f, fmaf(-pY, y, y)) * rY;

        // ---- E / num (parallel with rcp) ----
        float E    = fmaf(pow1, 55.0f, fmaf(pow2, -77.0f, -19.5f));
        float b2   = fmaf(0.02f, E, fmaf(2.0f, V, 0.02f));
        float num  = fmaf(-V, Gp, b2);
        float num9  = num * c9;
        float num12 = num * c12;
        float num01 = num * 0.01f;
        float numS  = num * (-cSIG);

        // ---- consume r: Vn + all ex2 args ----
        float Vn    = num * r;
        float dv25  = fmaf(num,   r, -25.0f);
        float dv35  = fmaf(num,   r,  35.0f);
        float dv01N = fmaf(num01, r, -0.25f);
        float dv01M = fmaf(num01, r,  0.35f);
        float argN  = fmaf(num9,  r, -25.0f * c9);
        float argM  = fmaf(num9,  r,  35.0f * c9);
        float argH  = fmaf(num12, r,  34.0f * c12);
        argS_prev   = fmaf(numS,  r, -20.0f * cSIG);

        float eN = ex2f_(argN);
        float eM = ex2f_(argM);
        float eH = ex2f_(argH);

        // ---- three rails interleaved (independent chains) ----
        float DN   = eN - 1.0f;
        float DM   = eM - 1.0f;
        float tH2  = eH * eH;
        float setN = fmaf(0.02f,  eN, 0.002f);
        float setM = fmaf(0.182f, eM, 0.124f);
        float qN   = dv01N * setN;
        float qM   = dv01M * setM;
        float wH   = fmaf(-0.0025f, tH2, eH - cAH01);
        float dN   = DN + qN;
        float dM   = DM + qM;
        float denH = fmaf( 0.0025f, tH2, eH + cAH01);
        float rrN  = rcpf_(dN);
        float rrM  = rcpf_(dM);
        float rrH  = rcpf_(denH);
        float scEN = (dv25 * eN) * 4.0e-4f;
        float scEM = (dv35 * eM) * (0.02f * 0.182f);
        float nmN  = fmaf(n, DN - qN, scEN);
        float nmM  = fmaf(m, DM - qM, scEM);
        float nmH  = fmaf(h, wH, 2.0f * cAH01);
        float resN = nmN * rrN;
        float resM = nmM * rrM;
        float resH = nmH * rrH;

        // reference's exact-equality singularity patches
        n = (dv25 == 0.0f) ? fmaf(n, kNp, cNp) : resN;
        m = (dv35 == 0.0f) ? fmaf(m, kMp, cMp) : resM;
        h = resH;
        y = yn;
        V = Vn;

        // stage off-spine values for next step
        h40 = 40.0f * h;
        yG  = fmaf(0.01f, yn, 1.003f);
    }

    // drain the pipelined output (row N_DIM-1)
    {
        float eS = ex2f_(argS_prev);
        *olPrev = rcpf_(1.0f + eS);
    }
}

extern "C" void kernel_launch(void* const* d_in, const int* in_sizes, int n_in,
                              void* d_out, int out_size) {
    const float* z = (const float*)d_in[0];
    float* out = (float*)d_out;
    // 1024 half-filled warps: 128 blocks x 256 threads -> 8 warps/SM, 2/SMSP
    hh_synaptic_kernel<<<128, 256>>>(z, out);
}